// round 2
// baseline (speedup 1.0000x reference)
#include <cuda_runtime.h>
#include <math.h>

// ---------------------------------------------------------------------------
// FourierAttn: out[q,k,b,h] = | prod_d sin(R_h*(qd-kd))/(qd-kd) |
//   head_q = (h @ Wq)  [1024,4,8,16],  head_k = (concat(mems,h) @ Wk) [2048,4,8,16]
//
// Identity: sin(R(q-k)) = sin(Rq)cos(Rk) - cos(Rq)sin(Rk), rd = Rq - Rk
//   val_d = R * g_d,  g_d = sin(rd)/rd  (or 1 - rd^2/6 when |rd| small)
//   out   = | R^16 * (prod_{d<8} s/rd) * (prod_{d>=8} s/rd) |   (2 fast divides)
// ---------------------------------------------------------------------------

#define QLEN 1024
#define MLEN 1024
#define KLEN 2048
#define BSZ  4
#define NH   8
#define DH   16
#define DM   128
#define BH   32   // BSZ*NH

#define TQ        2     // q's per thread
#define BLK_WARPS 8
#define QB        (BLK_WARPS * TQ)   // 16 q per block
#define KT        4     // k chunk staged in smem (32KB)
#define KR        512   // k range per block

#define SMALL_T   4e-3f

// Scratch tables: [pos][d][bh] of float4{rq, sin(rq), cos(rq), 0}
__device__ float4 g_qtab[QLEN * DH * BH];   // 8 MB
__device__ float4 g_ktab[KLEN * DH * BH];   // 16 MB

// ---------------------------------------------------------------------------
// Setup: projection (pos,b) row  @ W column, then R-scale + sincos
// ---------------------------------------------------------------------------
__global__ void __launch_bounds__(128)
proj_kernel(const float* __restrict__ h,
            const float* __restrict__ mems,
            const float* __restrict__ W,
            const float* __restrict__ paramR,
            int is_k)
{
    int pos = blockIdx.x;
    int b   = blockIdx.y;
    int n   = threadIdx.x;   // 0..127 = head*16 + d

    __shared__ float row[DM];
    const float* src;
    if (is_k)
        src = (pos < MLEN) ? (mems + ((size_t)pos * BSZ + b) * DM)
                           : (h    + ((size_t)(pos - MLEN) * BSZ + b) * DM);
    else
        src = h + ((size_t)pos * BSZ + b) * DM;
    row[n] = src[n];
    __syncthreads();

    float acc = 0.f;
#pragma unroll 8
    for (int m = 0; m < DM; m++)
        acc = fmaf(row[m], W[m * DM + n], acc);

    int hh = n >> 4;
    int d  = n & 15;
    float rq = paramR[hh] * acc;
    float s, c;
    sincosf(rq, &s, &c);   // accurate libm path, matches jnp.sin rounding closely

    float4 v = make_float4(rq, s, c, 0.f);
    if (is_k) g_ktab[((size_t)pos * DH + d) * BH + (b * NH + hh)] = v;
    else      g_qtab[((size_t)pos * DH + d) * BH + (b * NH + hh)] = v;
}

// ---------------------------------------------------------------------------
// Main kernel: block = 16 q  x  512 k range, lane = bh (coalesced stores)
// ---------------------------------------------------------------------------
__global__ void __launch_bounds__(256, 2)
fourier_kernel(const float* __restrict__ paramR, float* __restrict__ out)
{
    __shared__ float4 sk[KT * DH * BH];   // 32 KB

    const int lane  = threadIdx.x & 31;   // bh
    const int warp  = threadIdx.x >> 5;
    const int qbase = blockIdx.x * QB + warp * TQ;
    const int kbase = blockIdx.y * KR;

    // q-side registers: 2 q's x 16 dims x (rq, sin, cos)
    float qx[TQ][DH], qs[TQ][DH], qc[TQ][DH];
#pragma unroll
    for (int i = 0; i < TQ; i++)
#pragma unroll
        for (int d = 0; d < DH; d++) {
            float4 v = g_qtab[((size_t)(qbase + i) * DH + d) * BH + lane];
            qx[i][d] = v.x; qs[i][d] = v.y; qc[i][d] = v.z;
        }

    float R  = paramR[lane & 7];
    float r2 = R * R, r4 = r2 * r2, r8 = r4 * r4, r16 = r8 * r8;

    for (int k0 = kbase; k0 < kbase + KR; k0 += KT) {
        __syncthreads();
        // stage KT k-steps: contiguous 32KB copy, fully coalesced
        const float4* src = g_ktab + (size_t)k0 * DH * BH;
#pragma unroll
        for (int i = 0; i < (KT * DH * BH) / 256; i++)
            sk[threadIdx.x + i * 256] = src[threadIdx.x + i * 256];
        __syncthreads();

        for (int kk = 0; kk < KT; kk++) {
            float na[TQ], da[TQ], nb[TQ], db[TQ];
#pragma unroll
            for (int i = 0; i < TQ; i++) { na[i] = 1.f; da[i] = 1.f; nb[i] = 1.f; db[i] = 1.f; }

#pragma unroll
            for (int d = 0; d < DH; d++) {
                float4 kv = sk[(kk * DH + d) * BH + lane];
#pragma unroll
                for (int i = 0; i < TQ; i++) {
                    float rd = qx[i][d] - kv.x;                          // FADD
                    float s  = fmaf(qs[i][d], kv.z, -(qc[i][d] * kv.y)); // FMUL+FFMA
                    float u  = rd * rd;                                  // FMUL
                    float p  = fmaf(u, -0.16666667f, 1.f);               // FFMA (sinc Taylor)
                    bool  sm = fabsf(rd) < SMALL_T;
                    float nf = sm ? p   : s;                             // FSEL
                    float df = sm ? 1.f : rd;                            // FSEL
                    if (d < 8) { na[i] *= nf; da[i] *= df; }             // 2x FMUL
                    else       { nb[i] *= nf; db[i] *= df; }
                }
            }

            int k = k0 + kk;
#pragma unroll
            for (int i = 0; i < TQ; i++) {
                float ra = __fdividef(na[i], da[i]);   // |ra| <= 1, den >= (4e-3)^8 > 0
                float rb = __fdividef(nb[i], db[i]);
                out[(size_t)(qbase + i) * (KLEN * BH) + (size_t)k * BH + lane]
                    = fabsf(r16 * ra * rb);
            }
        }
    }
}

// ---------------------------------------------------------------------------
extern "C" void kernel_launch(void* const* d_in, const int* in_sizes, int n_in,
                              void* d_out, int out_size)
{
    (void)in_sizes; (void)n_in; (void)out_size;
    const float* h    = (const float*)d_in[0];
    const float* mems = (const float*)d_in[1];
    const float* Wq   = (const float*)d_in[2];
    const float* Wk   = (const float*)d_in[3];
    const float* R    = (const float*)d_in[4];

    proj_kernel<<<dim3(QLEN, BSZ), DM>>>(h, mems, Wq, R, 0);
    proj_kernel<<<dim3(KLEN, BSZ), DM>>>(h, mems, Wk, R, 1);

    dim3 grid(QLEN / QB, KLEN / KR);   // 64 x 4 = 256 blocks
    fourier_kernel<<<grid, BLK_WARPS * 32>>>(R, (float*)d_out);
}